// round 4
// baseline (speedup 1.0000x reference)
#include <cuda_runtime.h>
#include <cuda_pipeline.h>
#include <mma.h>
#include <math.h>

using namespace nvcuda;

#define T_   64
#define B_   256
#define NIN_ 1024
#define H_   2048
#define G_   8192   // 4*H

__device__ float g_A[(size_t)T_ * B_ * G_];
__device__ float g_HW[(size_t)B_ * G_];
__device__ float g_c[(size_t)B_ * H_];
__device__ float g_h[(size_t)B_ * H_];

__device__ __forceinline__ float to_tf32(float v)
{
    float r;
    asm("cvt.rna.tf32.f32 %0, %1;" : "=f"(r) : "f"(v));
    return r;
}

// ============================================================
// 3xTF32 tensor-core GEMM: C[M,N] = A[M,K] @ B[K,N], row-major fp32.
// Block tile 128x64, BK=16, 256 threads (8 warps, 4x2 warp grid,
// each warp 32x32 via 2x2 wmma m16n16k8 fragments).
// Each input split hi/lo; acc += ah*bl + al*bh + ah*bh  (fp32-like).
// cp.async double-buffered smem pipeline.
// Requires M%128==0, N%64==0, K%16==0.
// ============================================================
#define GBM 128
#define GBN 64
#define GBK 16
#define ALD 16   // As leading dim (floats)
#define BLD 72   // Bs leading dim (floats), padded vs 64

__global__ __launch_bounds__(256) void tf32x3_gemm_kernel(
    const float* __restrict__ A, const float* __restrict__ B,
    float* __restrict__ C, int M, int N, int K)
{
    __shared__ float As[2][GBM * ALD];
    __shared__ float Bs[2][GBK * BLD];

    const int tid = threadIdx.x;
    const float* Ab = A + (size_t)blockIdx.y * GBM * K;
    const float* Bb = B + (size_t)blockIdx.x * GBN;

    const int warp = tid >> 5;
    const int wm = warp & 3;
    const int wn = warp >> 2;

    wmma::fragment<wmma::accumulator, 16, 16, 8, float> acc[2][2];
    #pragma unroll
    for (int i = 0; i < 2; i++)
        #pragma unroll
        for (int j = 0; j < 2; j++)
            wmma::fill_fragment(acc[i][j], 0.0f);

    const int ar0 = tid >> 2;
    const int ac0 = (tid & 3) << 2;
    const int br  = tid >> 4;
    const int bc  = (tid & 15) << 2;

    const int NIT = K / GBK;

    {
        __pipeline_memcpy_async(&As[0][ar0 * ALD + ac0],
                                Ab + (size_t)ar0 * K + ac0, 16);
        __pipeline_memcpy_async(&As[0][(ar0 + 64) * ALD + ac0],
                                Ab + (size_t)(ar0 + 64) * K + ac0, 16);
        __pipeline_memcpy_async(&Bs[0][br * BLD + bc],
                                Bb + (size_t)br * N + bc, 16);
        __pipeline_commit();
    }

    for (int it = 0; it < NIT; ++it) {
        __pipeline_wait_prior(0);
        __syncthreads();
        const int cur = it & 1;
        if (it + 1 < NIT) {
            const int nxt = cur ^ 1;
            const int k0 = (it + 1) * GBK;
            __pipeline_memcpy_async(&As[nxt][ar0 * ALD + ac0],
                                    Ab + (size_t)ar0 * K + k0 + ac0, 16);
            __pipeline_memcpy_async(&As[nxt][(ar0 + 64) * ALD + ac0],
                                    Ab + (size_t)(ar0 + 64) * K + k0 + ac0, 16);
            __pipeline_memcpy_async(&Bs[nxt][br * BLD + bc],
                                    Bb + (size_t)(k0 + br) * N + bc, 16);
            __pipeline_commit();
        }

        #pragma unroll
        for (int ks = 0; ks < GBK; ks += 8) {
            wmma::fragment<wmma::matrix_a, 16, 16, 8, wmma::precision::tf32, wmma::row_major> ah[2], al[2];
            wmma::fragment<wmma::matrix_b, 16, 16, 8, wmma::precision::tf32, wmma::row_major> bh[2], bl[2];
            #pragma unroll
            for (int i = 0; i < 2; i++) {
                wmma::load_matrix_sync(ah[i], &As[cur][(wm * 32 + i * 16) * ALD + ks], ALD);
                #pragma unroll
                for (int e = 0; e < ah[i].num_elements; e++) {
                    float v  = ah[i].x[e];
                    float hi = to_tf32(v);
                    ah[i].x[e] = hi;
                    al[i].x[e] = to_tf32(v - hi);
                }
            }
            #pragma unroll
            for (int j = 0; j < 2; j++) {
                wmma::load_matrix_sync(bh[j], &Bs[cur][ks * BLD + wn * 32 + j * 16], BLD);
                #pragma unroll
                for (int e = 0; e < bh[j].num_elements; e++) {
                    float v  = bh[j].x[e];
                    float hi = to_tf32(v);
                    bh[j].x[e] = hi;
                    bl[j].x[e] = to_tf32(v - hi);
                }
            }
            #pragma unroll
            for (int i = 0; i < 2; i++)
                #pragma unroll
                for (int j = 0; j < 2; j++) {
                    wmma::mma_sync(acc[i][j], al[i], bh[j], acc[i][j]);
                    wmma::mma_sync(acc[i][j], ah[i], bl[j], acc[i][j]);
                    wmma::mma_sync(acc[i][j], ah[i], bh[j], acc[i][j]);
                }
        }
        __syncthreads();
    }

    float* Cb = C + (size_t)(blockIdx.y * GBM + wm * 32) * N
                  + (size_t)blockIdx.x * GBN + wn * 32;
    #pragma unroll
    for (int i = 0; i < 2; i++)
        #pragma unroll
        for (int j = 0; j < 2; j++)
            wmma::store_matrix_sync(Cb + (size_t)(i * 16) * N + j * 16,
                                    acc[i][j], N, wmma::mem_row_major);
}

// ============================================================
// Block reduction of (sum, sumsq) across 256 threads.
// ============================================================
__device__ __forceinline__ void blk_reduce2(float& s, float& s2)
{
    __shared__ float rbuf[2][8];
    const int lane = threadIdx.x & 31;
    const int warp = threadIdx.x >> 5;
    #pragma unroll
    for (int o = 16; o; o >>= 1) {
        s  += __shfl_down_sync(0xffffffffu, s,  o);
        s2 += __shfl_down_sync(0xffffffffu, s2, o);
    }
    if (lane == 0) { rbuf[0][warp] = s; rbuf[1][warp] = s2; }
    __syncthreads();
    if (warp == 0) {
        s  = (lane < 8) ? rbuf[0][lane] : 0.f;
        s2 = (lane < 8) ? rbuf[1][lane] : 0.f;
        #pragma unroll
        for (int o = 4; o; o >>= 1) {
            s  += __shfl_down_sync(0xffffffffu, s,  o);
            s2 += __shfl_down_sync(0xffffffffu, s2, o);
        }
        if (lane == 0) { rbuf[0][0] = s; rbuf[1][0] = s2; }
    }
    __syncthreads();
    s  = rbuf[0][0];
    s2 = rbuf[1][0];
    __syncthreads();
}

__global__ __launch_bounds__(256) void ln_rows_add_kernel(
    const float* __restrict__ Cin, const float* __restrict__ gamma,
    const float* __restrict__ beta, const float* __restrict__ bias,
    float* __restrict__ Aout)
{
    const int row = blockIdx.x;
    const float* x = Cin + (size_t)row * G_;
    float s = 0.f, s2 = 0.f;
    for (int j = threadIdx.x; j < G_; j += 256) {
        float v = x[j]; s += v; s2 += v * v;
    }
    blk_reduce2(s, s2);
    const float inv = 1.f / (float)G_;
    float mu   = s * inv;
    float var  = s2 * inv - mu * mu;
    float rstd = rsqrtf(var + 1e-5f);
    float* o = Aout + (size_t)row * G_;
    for (int j = threadIdx.x; j < G_; j += 256) {
        o[j] = (x[j] - mu) * rstd * gamma[j] + beta[j] + bias[j];
    }
}

__global__ void init_state_kernel(const float* __restrict__ init,
                                  const float* __restrict__ mask)
{
    int idx = blockIdx.x * blockDim.x + threadIdx.x;
    int b = idx >> 11;
    int j = idx & (H_ - 1);
    size_t base = (size_t)b * T_ * 2 * H_;
    g_c[idx] = init[base + j];
    g_h[idx] = init[base + H_ + j] * (1.f - mask[b]);
}

__global__ __launch_bounds__(256) void cell_kernel(
    int t, const float* __restrict__ mask,
    const float* __restrict__ A,
    const float* __restrict__ gh, const float* __restrict__ bh,
    const float* __restrict__ gc, const float* __restrict__ bc,
    float* __restrict__ hs)
{
    __shared__ float so[H_];
    const int b = blockIdx.x;
    const float keep = 1.f - mask[t * B_ + b];
    const float keep_next = (t + 1 < T_) ? (1.f - mask[(t + 1) * B_ + b]) : 1.f;
    const float* hw = g_HW + (size_t)b * G_;
    const float* a  = A + ((size_t)t * B_ + b) * G_;

    float s = 0.f, s2 = 0.f;
    for (int j = threadIdx.x; j < G_; j += 256) {
        float v = hw[j]; s += v; s2 += v * v;
    }
    blk_reduce2(s, s2);
    const float invG = 1.f / (float)G_;
    float mu   = s * invG;
    float rstd = rsqrtf(s2 * invG - mu * mu + 1e-5f);

    float cs = 0.f, cs2 = 0.f;
    for (int j = threadIdx.x; j < H_; j += 256) {
        float zi = a[j]          + (hw[j]          - mu) * rstd * gh[j]          + bh[j];
        float zf = a[H_ + j]     + (hw[H_ + j]     - mu) * rstd * gh[H_ + j]     + bh[H_ + j];
        float zo = a[2 * H_ + j] + (hw[2 * H_ + j] - mu) * rstd * gh[2 * H_ + j] + bh[2 * H_ + j];
        float zu = a[3 * H_ + j] + (hw[3 * H_ + j] - mu) * rstd * gh[3 * H_ + j] + bh[3 * H_ + j];
        float ig = 1.f / (1.f + expf(-zi));
        float fg = 1.f / (1.f + expf(-zf));
        float og = 1.f / (1.f + expf(-zo));
        float ug = tanhf(zu);
        float cn = fg * (g_c[(size_t)b * H_ + j] * keep) + ig * ug;
        g_c[(size_t)b * H_ + j] = cn;
        so[j] = og;
        cs += cn; cs2 += cn * cn;
    }
    blk_reduce2(cs, cs2);
    const float invH = 1.f / (float)H_;
    float muc   = cs * invH;
    float rstdc = rsqrtf(cs2 * invH - muc * muc + 1e-5f);

    for (int j = threadIdx.x; j < H_; j += 256) {
        float cn = g_c[(size_t)b * H_ + j];
        float hn = so[j] * tanhf((cn - muc) * rstdc * gc[j] + bc[j]);
        hs[((size_t)t * B_ + b) * H_ + j] = hn;
        g_h[(size_t)b * H_ + j] = hn * keep_next;
    }
}

__global__ void write_state_kernel(const float* __restrict__ hs,
                                   float* __restrict__ sout)
{
    int idx = blockIdx.x * blockDim.x + threadIdx.x;
    int b = idx >> 11;
    int j = idx & (H_ - 1);
    sout[(size_t)b * 2 * H_ + j] = g_c[idx];
    sout[(size_t)b * 2 * H_ + H_ + j] =
        hs[((size_t)(T_ - 1) * B_ + b) * H_ + j];
}

extern "C" void kernel_launch(void* const* d_in, const int* in_sizes, int n_in,
                              void* d_out, int out_size)
{
    const float* x    = (const float*)d_in[0];
    const float* mask = (const float*)d_in[1];
    const float* init = (const float*)d_in[2];
    const float* wx   = (const float*)d_in[3];
    const float* wh   = (const float*)d_in[4];
    const float* bvec = (const float*)d_in[5];
    const float* gx   = (const float*)d_in[6];
    const float* bx   = (const float*)d_in[7];
    const float* gh   = (const float*)d_in[8];
    const float* bh   = (const float*)d_in[9];
    const float* gc   = (const float*)d_in[10];
    const float* bc   = (const float*)d_in[11];

    float* out  = (float*)d_out;
    float* hs   = out;
    float* sout = out + (size_t)T_ * B_ * H_;

    float *Abuf, *HWbuf, *hbuf;
    cudaGetSymbolAddress((void**)&Abuf,  g_A);
    cudaGetSymbolAddress((void**)&HWbuf, g_HW);
    cudaGetSymbolAddress((void**)&hbuf,  g_h);

    tf32x3_gemm_kernel<<<dim3(G_ / GBN, (T_ * B_) / GBM), 256>>>(
        x, wx, Abuf, T_ * B_, G_, NIN_);
    ln_rows_add_kernel<<<T_ * B_, 256>>>(Abuf, gx, bx, bvec, Abuf);

    init_state_kernel<<<(B_ * H_) / 256, 256>>>(init, mask);

    for (int t = 0; t < T_; t++) {
        tf32x3_gemm_kernel<<<dim3(G_ / GBN, B_ / GBM), 256>>>(
            hbuf, wh, HWbuf, B_, G_, H_);
        cell_kernel<<<B_, 256>>>(t, mask, Abuf, gh, bh, gc, bc, hs);
    }

    write_state_kernel<<<(B_ * H_) / 256, 256>>>(hs, sout);
}